// round 1
// baseline (speedup 1.0000x reference)
#include <cuda_runtime.h>

// StoutSmearSlice: 24^4 lattice, 4 directions, 3x3 complex links (separate re/im
// fp32 arrays). MU=0, update EVEN parity subset only.
//
// Inputs (metadata order): x_re [4,24,24,24,24,3,3] f32, x_im same, coeff[6] f32.
// Output: [4,24,24,24,24,3,3,2] f32 (re/im interleaved).
//
// Odd sites of dir 0 and all of dirs 1..3 are unchanged -> copy kernel.
// Even sites of dir 0 get the stout update -> compute kernel.

#define LD 24
#define IDX9(d,t,z,y,x) ((((((d)*24+(t))*24+(z))*24+(y))*24+(x))*9)

struct M3 { float re[9], im[9]; };

__device__ __forceinline__ void mload(M3 &A, const float* __restrict__ re,
                                      const float* __restrict__ im, int b) {
#pragma unroll
    for (int i = 0; i < 9; i++) { A.re[i] = re[b + i]; A.im[i] = im[b + i]; }
}

// C = A @ B
__device__ __forceinline__ void mmul(M3 &C, const M3 &A, const M3 &B) {
#pragma unroll
    for (int r = 0; r < 3; r++) {
#pragma unroll
        for (int c = 0; c < 3; c++) {
            float sr = 0.f, si = 0.f;
#pragma unroll
            for (int k = 0; k < 3; k++) {
                float ar = A.re[r*3+k], ai = A.im[r*3+k];
                float br = B.re[k*3+c], bi = B.im[k*3+c];
                sr = fmaf(ar, br, sr); sr = fmaf(-ai, bi, sr);
                si = fmaf(ar, bi, si); si = fmaf(ai, br, si);
            }
            C.re[r*3+c] = sr; C.im[r*3+c] = si;
        }
    }
}

// C = A @ B^dag
__device__ __forceinline__ void mmul_nd(M3 &C, const M3 &A, const M3 &B) {
#pragma unroll
    for (int r = 0; r < 3; r++) {
#pragma unroll
        for (int c = 0; c < 3; c++) {
            float sr = 0.f, si = 0.f;
#pragma unroll
            for (int k = 0; k < 3; k++) {
                float ar = A.re[r*3+k], ai = A.im[r*3+k];
                float br = B.re[c*3+k], bi = B.im[c*3+k];   // conj(B[c][k])
                sr = fmaf(ar, br, sr); sr = fmaf(ai, bi, sr);
                si = fmaf(ai, br, si); si = fmaf(-ar, bi, si);
            }
            C.re[r*3+c] = sr; C.im[r*3+c] = si;
        }
    }
}

// C = A^dag @ B
__device__ __forceinline__ void mmul_dn(M3 &C, const M3 &A, const M3 &B) {
#pragma unroll
    for (int r = 0; r < 3; r++) {
#pragma unroll
        for (int c = 0; c < 3; c++) {
            float sr = 0.f, si = 0.f;
#pragma unroll
            for (int k = 0; k < 3; k++) {
                float ar = A.re[k*3+r], ai = A.im[k*3+r];   // conj(A[k][r])
                float br = B.re[k*3+c], bi = B.im[k*3+c];
                sr = fmaf(ar, br, sr); sr = fmaf(ai, bi, sr);
                si = fmaf(ar, bi, si); si = fmaf(-ai, br, si);
            }
            C.re[r*3+c] = sr; C.im[r*3+c] = si;
        }
    }
}

__device__ __forceinline__ void macc(M3 &F, const M3 &T, float c) {
#pragma unroll
    for (int i = 0; i < 9; i++) {
        F.re[i] = fmaf(c, T.re[i], F.re[i]);
        F.im[i] = fmaf(c, T.im[i], F.im[i]);
    }
}

// One nu-direction: forward staple (coeff cf) + backward staple (coeff cb).
// stf(s)      = Unu(s)      @ U0(s+nu)  @ Unu(s+mu)^dag
// stu(s-nu)   = Unu(s-nu)^dag @ U0(s-nu) @ Unu(s-nu+mu)
__device__ __forceinline__ void staple_pair(M3 &f,
        const float* __restrict__ xre, const float* __restrict__ xim,
        int b0p, int b0m, int bns, int bnsmu, int bnm, int bnmmu,
        float cf, float cb) {
    M3 A, B, C3, T1, T2;
    mload(A, xre, xim, b0p);        // U0(s+nu)
    mload(B, xre, xim, bnsmu);      // Unu(s+mu)
    mmul_nd(T1, A, B);
    mload(C3, xre, xim, bns);       // Unu(s)
    mmul(T2, C3, T1);
    macc(f, T2, cf);

    mload(A, xre, xim, bnm);        // Unu(s-nu)
    mload(B, xre, xim, b0m);        // U0(s-nu)
    mmul_dn(T1, A, B);
    mload(C3, xre, xim, bnmmu);     // Unu(s-nu+mu)
    mmul(T2, T1, C3);
    macc(f, T2, cb);
}

// Copy everything (re/im interleave). Compute kernel overwrites dir-0 even sites.
// Processes 4 complex elements per thread via float4.
__global__ void copy_interleave(const float4* __restrict__ re,
                                const float4* __restrict__ im,
                                float4* __restrict__ out, int n4) {
    int i = blockIdx.x * blockDim.x + threadIdx.x;
    if (i < n4) {
        float4 r = re[i], m = im[i];
        out[2*i]     = make_float4(r.x, m.x, r.y, m.y);
        out[2*i + 1] = make_float4(r.z, m.z, r.w, m.w);
    }
}

__global__ void stout_update(const float* __restrict__ xre,
                             const float* __restrict__ xim,
                             const float* __restrict__ coeff,
                             float2* __restrict__ out) {
    const int NSITE = 24 * 24 * 24 * 12;   // even sites
    int tid = blockIdx.x * blockDim.x + threadIdx.x;
    if (tid >= NSITE) return;

    int xi = tid % 12; int r = tid / 12;
    int y = r % 24; r /= 24;
    int z = r % 24; r /= 24;
    int t = r;
    int x = 2 * xi + ((t + z + y) & 1);     // (t+z+y+x) even

    int tp = (t + 1) % 24;
    int zp = (z + 1) % 24, zm = (z + 23) % 24;
    int yp = (y + 1) % 24, ym = (y + 23) % 24;
    int xp = (x + 1) % 24, xm = (x + 23) % 24;

    // scale_coeff(coeff, 0.75) = (2/pi)*0.75*atan(coeff)
    float c[6];
#pragma unroll
    for (int i = 0; i < 6; i++) c[i] = 0.47746482927568606f * atanf(coeff[i]);

    M3 f;
#pragma unroll
    for (int i = 0; i < 9; i++) { f.re[i] = 0.f; f.im[i] = 0.f; }

    // nu = 1 (Z axis)
    staple_pair(f, xre, xim,
                IDX9(0,t,zp,y,x), IDX9(0,t,zm,y,x),
                IDX9(1,t,z,y,x),  IDX9(1,tp,z,y,x),
                IDX9(1,t,zm,y,x), IDX9(1,tp,zm,y,x),
                c[0], c[1]);
    // nu = 2 (Y axis)
    staple_pair(f, xre, xim,
                IDX9(0,t,z,yp,x), IDX9(0,t,z,ym,x),
                IDX9(2,t,z,y,x),  IDX9(2,tp,z,y,x),
                IDX9(2,t,z,ym,x), IDX9(2,tp,z,ym,x),
                c[2], c[3]);
    // nu = 3 (X axis)
    staple_pair(f, xre, xim,
                IDX9(0,t,z,y,xp), IDX9(0,t,z,y,xm),
                IDX9(3,t,z,y,x),  IDX9(3,tp,z,y,x),
                IDX9(3,t,z,y,xm), IDX9(3,tp,z,y,xm),
                c[4], c[5]);

    const float inv6 = 1.0f / 6.0f;
#pragma unroll
    for (int i = 0; i < 9; i++) { f.re[i] *= inv6; f.im[i] *= inv6; }

    int b0 = IDX9(0, t, z, y, x);
    M3 U0; mload(U0, xre, xim, b0);

    // M = f @ U0^dag ; A = 0.5*(M - M^dag) ; Z = A - tr(A)/3 * I ; Z *= 2^-4
    M3 Mm; mmul_nd(Mm, f, U0);
    M3 Z;
#pragma unroll
    for (int rr = 0; rr < 3; rr++) {
#pragma unroll
        for (int cc = 0; cc < 3; cc++) {
            Z.re[rr*3+cc] = 0.5f * (Mm.re[rr*3+cc] - Mm.re[cc*3+rr]);
            Z.im[rr*3+cc] = 0.5f * (Mm.im[rr*3+cc] + Mm.im[cc*3+rr]);
        }
    }
    float trr = (Z.re[0] + Z.re[4] + Z.re[8]) * (1.0f / 3.0f);
    float tri = (Z.im[0] + Z.im[4] + Z.im[8]) * (1.0f / 3.0f);
    Z.re[0] -= trr; Z.re[4] -= trr; Z.re[8] -= trr;
    Z.im[0] -= tri; Z.im[4] -= tri; Z.im[8] -= tri;
#pragma unroll
    for (int i = 0; i < 9; i++) { Z.re[i] *= 0.0625f; Z.im[i] *= 0.0625f; }

    // Horner Taylor, 12 terms: E = I + (Z@E)/k
    M3 E, T1;
#pragma unroll
    for (int i = 0; i < 9; i++) { E.re[i] = (i % 4 == 0) ? 1.f : 0.f; E.im[i] = 0.f; }
#pragma unroll
    for (int k = 12; k >= 1; k--) {
        mmul(T1, Z, E);
        float inv = 1.0f / (float)k;
#pragma unroll
        for (int i = 0; i < 9; i++) {
            E.re[i] = fmaf(T1.re[i], inv, (i % 4 == 0) ? 1.f : 0.f);
            E.im[i] = T1.im[i] * inv;
        }
    }
    // 4 squarings
#pragma unroll
    for (int s = 0; s < 4; s++) { mmul(T1, E, E); E = T1; }

    // y_mu = E @ U0 (on even sites xmu_fix = 0)
    M3 Y; mmul(Y, E, U0);
#pragma unroll
    for (int i = 0; i < 9; i++) out[b0 + i] = make_float2(Y.re[i], Y.im[i]);
}

extern "C" void kernel_launch(void* const* d_in, const int* in_sizes, int n_in,
                              void* d_out, int out_size) {
    const float* xre   = (const float*)d_in[0];
    const float* xim   = (const float*)d_in[1];
    const float* coeff = (const float*)d_in[2];

    int n  = in_sizes[0];          // 4*24^4*9 = 11,943,936 complex elements
    int n4 = n / 4;
    copy_interleave<<<(n4 + 255) / 256, 256>>>(
        (const float4*)xre, (const float4*)xim, (float4*)d_out, n4);

    const int NSITE = 24 * 24 * 24 * 12;
    stout_update<<<(NSITE + 127) / 128, 128>>>(xre, xim, coeff, (float2*)d_out);
}

// round 2
// speedup vs baseline: 1.1948x; 1.1948x over previous
#include <cuda_runtime.h>

// StoutSmearSlice: 24^4 lattice, 4 dirs, 3x3 complex links (separate re/im fp32).
// MU=0, update EVEN parity sites of dir 0; everything else is a copy.
//
// Fused single kernel:
//   blocks [0, NCB)        : 1 thread = 1 even site. Stout update for the even
//                            site + plain copy of the paired odd site (x^1).
//   blocks [NCB, NCB+NCPB) : float4 re/im interleave copy of dirs 1..3.
// All writes disjoint; reads only touch the const input arrays.

#define IDX9(d,t,z,y,x) ((((((d)*24+(t))*24+(z))*24+(y))*24+(x))*9)

static const int NSITE  = 24 * 24 * 24 * 12;          // even sites = 165888
static const int NCB    = NSITE / 128;                // 1296 compute blocks
static const int DIR_F  = 24 * 24 * 24 * 24 * 9;      // floats per direction
static const int COPY4  = 3 * DIR_F / 4;              // float4s in dirs 1..3 = 2239488
static const int PER_B  = 128 * 4;                    // float4s per copy block
static const int NCPB   = COPY4 / PER_B;              // 4374 copy blocks

struct M3 { float re[9], im[9]; };

__device__ __forceinline__ void mload(M3 &A, const float* __restrict__ re,
                                      const float* __restrict__ im, int b) {
#pragma unroll
    for (int i = 0; i < 9; i++) { A.re[i] = re[b + i]; A.im[i] = im[b + i]; }
}

// C = A @ B
__device__ __forceinline__ void mmul(M3 &C, const M3 &A, const M3 &B) {
#pragma unroll
    for (int r = 0; r < 3; r++)
#pragma unroll
        for (int c = 0; c < 3; c++) {
            float sr = 0.f, si = 0.f;
#pragma unroll
            for (int k = 0; k < 3; k++) {
                float ar = A.re[r*3+k], ai = A.im[r*3+k];
                float br = B.re[k*3+c], bi = B.im[k*3+c];
                sr = fmaf(ar, br, sr); sr = fmaf(-ai, bi, sr);
                si = fmaf(ar, bi, si); si = fmaf(ai, br, si);
            }
            C.re[r*3+c] = sr; C.im[r*3+c] = si;
        }
}

// C = A @ B^dag
__device__ __forceinline__ void mmul_nd(M3 &C, const M3 &A, const M3 &B) {
#pragma unroll
    for (int r = 0; r < 3; r++)
#pragma unroll
        for (int c = 0; c < 3; c++) {
            float sr = 0.f, si = 0.f;
#pragma unroll
            for (int k = 0; k < 3; k++) {
                float ar = A.re[r*3+k], ai = A.im[r*3+k];
                float br = B.re[c*3+k], bi = B.im[c*3+k];
                sr = fmaf(ar, br, sr); sr = fmaf(ai, bi, sr);
                si = fmaf(ai, br, si); si = fmaf(-ar, bi, si);
            }
            C.re[r*3+c] = sr; C.im[r*3+c] = si;
        }
}

// C = A^dag @ B
__device__ __forceinline__ void mmul_dn(M3 &C, const M3 &A, const M3 &B) {
#pragma unroll
    for (int r = 0; r < 3; r++)
#pragma unroll
        for (int c = 0; c < 3; c++) {
            float sr = 0.f, si = 0.f;
#pragma unroll
            for (int k = 0; k < 3; k++) {
                float ar = A.re[k*3+r], ai = A.im[k*3+r];
                float br = B.re[k*3+c], bi = B.im[k*3+c];
                sr = fmaf(ar, br, sr); sr = fmaf(ai, bi, sr);
                si = fmaf(ar, bi, si); si = fmaf(-ai, br, si);
            }
            C.re[r*3+c] = sr; C.im[r*3+c] = si;
        }
}

__device__ __forceinline__ void macc(M3 &F, const M3 &T, float c) {
#pragma unroll
    for (int i = 0; i < 9; i++) {
        F.re[i] = fmaf(c, T.re[i], F.re[i]);
        F.im[i] = fmaf(c, T.im[i], F.im[i]);
    }
}

// Forward staple (cf) + backward staple (cb) for one nu direction.
__device__ __forceinline__ void staple_pair(M3 &f,
        const float* __restrict__ xre, const float* __restrict__ xim,
        int b0p, int b0m, int bns, int bnsmu, int bnm, int bnmmu,
        float cf, float cb) {
    M3 A, B, C3, T1, T2;
    mload(A, xre, xim, b0p);        // U0(s+nu)
    mload(B, xre, xim, bnsmu);      // Unu(s+mu)
    mmul_nd(T1, A, B);
    mload(C3, xre, xim, bns);       // Unu(s)
    mmul(T2, C3, T1);
    macc(f, T2, cf);

    mload(A, xre, xim, bnm);        // Unu(s-nu)
    mload(B, xre, xim, b0m);        // U0(s-nu)
    mmul_dn(T1, A, B);
    mload(C3, xre, xim, bnmmu);     // Unu(s-nu+mu)
    mmul(T2, T1, C3);
    macc(f, T2, cb);
}

__global__ __launch_bounds__(128) void stout_fused(
        const float* __restrict__ xre,
        const float* __restrict__ xim,
        const float* __restrict__ coeff,
        float2* __restrict__ out) {
    if (blockIdx.x >= NCB) {
        // ---- copy role: dirs 1..3, float4 interleave ----
        const float4* re4 = (const float4*)(xre + DIR_F);
        const float4* im4 = (const float4*)(xim + DIR_F);
        float4* o4 = (float4*)(out + DIR_F);   // out elements are float2; dir1 base
        int base = (blockIdx.x - NCB) * PER_B + threadIdx.x;
#pragma unroll
        for (int k = 0; k < 4; k++) {
            int i = base + k * 128;
            float4 r = re4[i], m = im4[i];
            o4[2*i]     = make_float4(r.x, m.x, r.y, m.y);
            o4[2*i + 1] = make_float4(r.z, m.z, r.w, m.w);
        }
        return;
    }

    // ---- compute role: one even site ----
    int tid = blockIdx.x * 128 + threadIdx.x;
    int xi = tid % 12; int r = tid / 12;
    int y = r % 24; r /= 24;
    int z = r % 24; r /= 24;
    int t = r;
    int x = 2 * xi + ((t + z + y) & 1);      // (t+z+y+x) even

    // copy the paired odd site of dir 0 first (latency hidden by staple work)
    {
        int bo = IDX9(0, t, z, y, x ^ 1);
#pragma unroll
        for (int i = 0; i < 9; i++)
            out[bo + i] = make_float2(xre[bo + i], xim[bo + i]);
    }

    int tp = (t + 1) % 24;
    int zp = (z + 1) % 24, zm = (z + 23) % 24;
    int yp = (y + 1) % 24, ym = (y + 23) % 24;
    int xp = (x + 1) % 24, xm = (x + 23) % 24;

    // scale_coeff(coeff, 0.75) = (2/pi)*0.75*atan(coeff)
    float c[6];
#pragma unroll
    for (int i = 0; i < 6; i++) c[i] = 0.47746482927568606f * atanf(coeff[i]);

    M3 f;
#pragma unroll
    for (int i = 0; i < 9; i++) { f.re[i] = 0.f; f.im[i] = 0.f; }

    staple_pair(f, xre, xim,                     // nu = 1 (Z)
                IDX9(0,t,zp,y,x), IDX9(0,t,zm,y,x),
                IDX9(1,t,z,y,x),  IDX9(1,tp,z,y,x),
                IDX9(1,t,zm,y,x), IDX9(1,tp,zm,y,x),
                c[0], c[1]);
    staple_pair(f, xre, xim,                     // nu = 2 (Y)
                IDX9(0,t,z,yp,x), IDX9(0,t,z,ym,x),
                IDX9(2,t,z,y,x),  IDX9(2,tp,z,y,x),
                IDX9(2,t,z,ym,x), IDX9(2,tp,z,ym,x),
                c[2], c[3]);
    staple_pair(f, xre, xim,                     // nu = 3 (X)
                IDX9(0,t,z,y,xp), IDX9(0,t,z,y,xm),
                IDX9(3,t,z,y,x),  IDX9(3,tp,z,y,x),
                IDX9(3,t,z,y,xm), IDX9(3,tp,z,y,xm),
                c[4], c[5]);

    const float inv6 = 1.0f / 6.0f;
#pragma unroll
    for (int i = 0; i < 9; i++) { f.re[i] *= inv6; f.im[i] *= inv6; }

    int b0 = IDX9(0, t, z, y, x);
    M3 U0; mload(U0, xre, xim, b0);

    // Z = projectTangent(f @ U0^dag), pre-scaled by 2^-4
    M3 Mm; mmul_nd(Mm, f, U0);
    M3 Z;
#pragma unroll
    for (int rr = 0; rr < 3; rr++)
#pragma unroll
        for (int cc = 0; cc < 3; cc++) {
            Z.re[rr*3+cc] = 0.5f * (Mm.re[rr*3+cc] - Mm.re[cc*3+rr]);
            Z.im[rr*3+cc] = 0.5f * (Mm.im[rr*3+cc] + Mm.im[cc*3+rr]);
        }
    float trr = (Z.re[0] + Z.re[4] + Z.re[8]) * (1.0f / 3.0f);
    float tri = (Z.im[0] + Z.im[4] + Z.im[8]) * (1.0f / 3.0f);
    Z.re[0] -= trr; Z.re[4] -= trr; Z.re[8] -= trr;
    Z.im[0] -= tri; Z.im[4] -= tri; Z.im[8] -= tri;
#pragma unroll
    for (int i = 0; i < 9; i++) { Z.re[i] *= 0.0625f; Z.im[i] *= 0.0625f; }

    // Horner Taylor, 12 terms
    M3 E, T1;
#pragma unroll
    for (int i = 0; i < 9; i++) { E.re[i] = (i % 4 == 0) ? 1.f : 0.f; E.im[i] = 0.f; }
#pragma unroll
    for (int k = 12; k >= 1; k--) {
        mmul(T1, Z, E);
        float inv = 1.0f / (float)k;
#pragma unroll
        for (int i = 0; i < 9; i++) {
            E.re[i] = fmaf(T1.re[i], inv, (i % 4 == 0) ? 1.f : 0.f);
            E.im[i] = T1.im[i] * inv;
        }
    }
    // 4 squarings
#pragma unroll
    for (int s = 0; s < 4; s++) { mmul(T1, E, E); E = T1; }

    // y_mu = E @ U0 (even sites: xmu_fix = 0)
    M3 Y; mmul(Y, E, U0);
#pragma unroll
    for (int i = 0; i < 9; i++) out[b0 + i] = make_float2(Y.re[i], Y.im[i]);
}

extern "C" void kernel_launch(void* const* d_in, const int* in_sizes, int n_in,
                              void* d_out, int out_size) {
    const float* xre   = (const float*)d_in[0];
    const float* xim   = (const float*)d_in[1];
    const float* coeff = (const float*)d_in[2];

    stout_fused<<<NCB + NCPB, 128>>>(xre, xim, coeff, (float2*)d_out);
}

// round 3
// speedup vs baseline: 1.2484x; 1.0448x over previous
#include <cuda_runtime.h>

// StoutSmearSlice: 24^4 lattice, 4 dirs, 3x3 complex links (separate re/im fp32).
// MU=0, update EVEN parity sites of dir 0; everything else is a copy.
//
// Round 3: all complex arithmetic packed into fma.rn.f32x2 (sm_103a FFMA2).
// A complex inner product keeps two packed accumulators:
//   acc1 = sum {ar,ar} * {br,bi}   (= {sum ar*br, sum ar*bi})
//   acc2 = sum {ai,ai} * {br,bi}   (= {sum ai*br, sum ai*bi})
// and combines per conjugation mode:
//   NN   : cr = acc1.x - acc2.y ; ci = acc1.y + acc2.x
//   A@B^ : cr = acc1.x + acc2.y ; ci = acc2.x - acc1.y   (b indices transposed)
//   A^@B : cr = acc1.x + acc2.y ; ci = acc1.y - acc2.x   (a indices transposed)

#define IDX9(d,t,z,y,x) ((((((d)*24+(t))*24+(z))*24+(y))*24+(x))*9)

static const int NSITE  = 24 * 24 * 24 * 12;          // even sites = 165888
static const int NCB    = NSITE / 128;                // 1296 compute blocks
static const int DIR_F  = 24 * 24 * 24 * 24 * 9;      // floats per direction
static const int COPY4  = 3 * DIR_F / 4;              // float4s in dirs 1..3
static const int PER_B  = 128 * 4;                    // float4s per copy block
static const int NCPB   = COPY4 / PER_B;              // 4374 copy blocks

typedef unsigned long long c64;   // packed {lo=re, hi=im} fp32 pair

__device__ __forceinline__ c64 pk(float lo, float hi) {
    c64 r; asm("mov.b64 %0,{%1,%2};" : "=l"(r) : "f"(lo), "f"(hi)); return r;
}
__device__ __forceinline__ void upk(c64 v, float &lo, float &hi) {
    asm("mov.b64 {%0,%1},%2;" : "=f"(lo), "=f"(hi) : "l"(v));
}
__device__ __forceinline__ c64 fma2(c64 a, c64 b, c64 c) {
    c64 d; asm("fma.rn.f32x2 %0,%1,%2,%3;" : "=l"(d) : "l"(a), "l"(b), "l"(c));
    return d;
}
__device__ __forceinline__ c64 mul2(c64 a, c64 b) {
    c64 d; asm("mul.rn.f32x2 %0,%1,%2;" : "=l"(d) : "l"(a), "l"(b)); return d;
}

struct C3 { c64 m[9]; };

__device__ __forceinline__ void mload(C3 &A, const float* __restrict__ re,
                                      const float* __restrict__ im, int b) {
#pragma unroll
    for (int i = 0; i < 9; i++) A.m[i] = pk(re[b + i], im[b + i]);
}

// MODE: 0 = A@B, 1 = A@B^dag, 2 = A^dag@B
template <int MODE>
__device__ __forceinline__ void cmul(C3 &C, const C3 &A, const C3 &B) {
#pragma unroll
    for (int r = 0; r < 3; r++) {
        float ar[3], ai[3];
#pragma unroll
        for (int k = 0; k < 3; k++)
            upk(A.m[MODE == 2 ? k * 3 + r : r * 3 + k], ar[k], ai[k]);
        c64 arr[3], aii[3];
#pragma unroll
        for (int k = 0; k < 3; k++) { arr[k] = pk(ar[k], ar[k]); aii[k] = pk(ai[k], ai[k]); }
#pragma unroll
        for (int c = 0; c < 3; c++) {
            c64 b0 = B.m[MODE == 1 ? c * 3 + 0 : 0 * 3 + c];
            c64 acc1 = mul2(arr[0], b0);
            c64 acc2 = mul2(aii[0], b0);
#pragma unroll
            for (int k = 1; k < 3; k++) {
                c64 b = B.m[MODE == 1 ? c * 3 + k : k * 3 + c];
                acc1 = fma2(arr[k], b, acc1);
                acc2 = fma2(aii[k], b, acc2);
            }
            float x1, y1, x2, y2;
            upk(acc1, x1, y1); upk(acc2, x2, y2);
            float cr, ci;
            if (MODE == 0)      { cr = x1 - y2; ci = y1 + x2; }
            else if (MODE == 1) { cr = x1 + y2; ci = x2 - y1; }
            else                { cr = x1 + y2; ci = y1 - x2; }
            C.m[r * 3 + c] = pk(cr, ci);
        }
    }
}

__device__ __forceinline__ void macc(C3 &F, const C3 &T, c64 cc) {
#pragma unroll
    for (int i = 0; i < 9; i++) F.m[i] = fma2(cc, T.m[i], F.m[i]);
}

// Forward staple (cf) + backward staple (cb) for one nu direction.
__device__ __forceinline__ void staple_pair(C3 &f,
        const float* __restrict__ xre, const float* __restrict__ xim,
        int b0p, int b0m, int bns, int bnsmu, int bnm, int bnmmu,
        c64 cf, c64 cb) {
    C3 A, B, C, T1, T2;
    mload(A, xre, xim, b0p);        // U0(s+nu)
    mload(B, xre, xim, bnsmu);      // Unu(s+mu)
    cmul<1>(T1, A, B);              // U0(s+nu) @ Unu(s+mu)^dag
    mload(C, xre, xim, bns);        // Unu(s)
    cmul<0>(T2, C, T1);
    macc(f, T2, cf);

    mload(A, xre, xim, bnm);        // Unu(s-nu)
    mload(B, xre, xim, b0m);        // U0(s-nu)
    cmul<2>(T1, A, B);              // Unu(s-nu)^dag @ U0(s-nu)
    mload(C, xre, xim, bnmmu);      // Unu(s-nu+mu)
    cmul<0>(T2, T1, C);
    macc(f, T2, cb);
}

__global__ __launch_bounds__(128, 6) void stout_fused(
        const float* __restrict__ xre,
        const float* __restrict__ xim,
        const float* __restrict__ coeff,
        float2* __restrict__ out) {
    if (blockIdx.x >= NCB) {
        // ---- copy role: dirs 1..3, float4 interleave ----
        const float4* re4 = (const float4*)(xre + DIR_F);
        const float4* im4 = (const float4*)(xim + DIR_F);
        float4* o4 = (float4*)(out + DIR_F);
        int base = (blockIdx.x - NCB) * PER_B + threadIdx.x;
#pragma unroll
        for (int k = 0; k < 4; k++) {
            int i = base + k * 128;
            float4 r = re4[i], m = im4[i];
            o4[2*i]     = make_float4(r.x, m.x, r.y, m.y);
            o4[2*i + 1] = make_float4(r.z, m.z, r.w, m.w);
        }
        return;
    }

    // ---- compute role: one even site ----
    int tid = blockIdx.x * 128 + threadIdx.x;
    int xi = tid % 12; int r = tid / 12;
    int y = r % 24; r /= 24;
    int z = r % 24; r /= 24;
    int t = r;
    int x = 2 * xi + ((t + z + y) & 1);      // (t+z+y+x) even

    c64* out64 = (c64*)out;

    // copy the paired odd site of dir 0 (latency hidden by staple work)
    {
        int bo = IDX9(0, t, z, y, x ^ 1);
#pragma unroll
        for (int i = 0; i < 9; i++) out64[bo + i] = pk(xre[bo + i], xim[bo + i]);
    }

    int tp = (t + 1) % 24;
    int zp = (z + 1) % 24, zm = (z + 23) % 24;
    int yp = (y + 1) % 24, ym = (y + 23) % 24;
    int xp = (x + 1) % 24, xm = (x + 23) % 24;

    // scale_coeff(coeff,0.75) = (2/pi)*0.75*atan(c); fold the /6 of the staple
    // average in here so f already includes it.
    c64 c[6];
#pragma unroll
    for (int i = 0; i < 6; i++) {
        float v = (0.47746482927568606f / 6.0f) * atanf(coeff[i]);
        c[i] = pk(v, v);
    }

    C3 f;
#pragma unroll
    for (int i = 0; i < 9; i++) f.m[i] = 0ull;

    staple_pair(f, xre, xim,                     // nu = 1 (Z)
                IDX9(0,t,zp,y,x), IDX9(0,t,zm,y,x),
                IDX9(1,t,z,y,x),  IDX9(1,tp,z,y,x),
                IDX9(1,t,zm,y,x), IDX9(1,tp,zm,y,x),
                c[0], c[1]);
    staple_pair(f, xre, xim,                     // nu = 2 (Y)
                IDX9(0,t,z,yp,x), IDX9(0,t,z,ym,x),
                IDX9(2,t,z,y,x),  IDX9(2,tp,z,y,x),
                IDX9(2,t,z,ym,x), IDX9(2,tp,z,ym,x),
                c[2], c[3]);
    staple_pair(f, xre, xim,                     // nu = 3 (X)
                IDX9(0,t,z,y,xp), IDX9(0,t,z,y,xm),
                IDX9(3,t,z,y,x),  IDX9(3,tp,z,y,x),
                IDX9(3,t,z,y,xm), IDX9(3,tp,z,y,xm),
                c[4], c[5]);

    int b0 = IDX9(0, t, z, y, x);
    C3 U0; mload(U0, xre, xim, b0);

    // M = f @ U0^dag ; Z = (projectTangent scaled by 2^-4)
    // Z_off = 0.03125*(M - M^dag); diag re = 0; diag im -= trace_im/3.
    C3 Mm; cmul<1>(Mm, f, U0);
    float mr[9], mi[9];
#pragma unroll
    for (int i = 0; i < 9; i++) upk(Mm.m[i], mr[i], mi[i]);
    const float s = 0.03125f;   // 0.5 * 2^-4
    float zre[9], zim[9];
#pragma unroll
    for (int rr = 0; rr < 3; rr++)
#pragma unroll
        for (int cc = 0; cc < 3; cc++) {
            zre[rr*3+cc] = s * (mr[rr*3+cc] - mr[cc*3+rr]);
            zim[rr*3+cc] = s * (mi[rr*3+cc] + mi[cc*3+rr]);
        }
    float tri = (zim[0] + zim[4] + zim[8]) * (1.0f / 3.0f);
    zim[0] -= tri; zim[4] -= tri; zim[8] -= tri;
    C3 Z;
#pragma unroll
    for (int i = 0; i < 9; i++) Z.m[i] = pk(zre[i], zim[i]);

    // Horner Taylor, 12 terms: E = I + (Z@E)/k
    const c64 one = pk(1.0f, 0.0f);
    C3 E, T1;
#pragma unroll
    for (int i = 0; i < 9; i++) E.m[i] = (i % 4 == 0) ? one : 0ull;
#pragma unroll
    for (int k = 12; k >= 1; k--) {
        cmul<0>(T1, Z, E);
        float inv = 1.0f / (float)k;
        c64 inv2 = pk(inv, inv);
#pragma unroll
        for (int i = 0; i < 9; i++)
            E.m[i] = fma2(T1.m[i], inv2, (i % 4 == 0) ? one : 0ull);
    }
    // 4 squarings
#pragma unroll
    for (int sq = 0; sq < 4; sq++) { cmul<0>(T1, E, E); E = T1; }

    // y_mu = E @ U0 (even sites: xmu_fix = 0)
    C3 Y; cmul<0>(Y, E, U0);
#pragma unroll
    for (int i = 0; i < 9; i++) out64[b0 + i] = Y.m[i];
}

extern "C" void kernel_launch(void* const* d_in, const int* in_sizes, int n_in,
                              void* d_out, int out_size) {
    const float* xre   = (const float*)d_in[0];
    const float* xim   = (const float*)d_in[1];
    const float* coeff = (const float*)d_in[2];

    stout_fused<<<NCB + NCPB, 128>>>(xre, xim, coeff, (float2*)d_out);
}

// round 4
// speedup vs baseline: 1.3611x; 1.0903x over previous
#include <cuda_runtime.h>

// StoutSmearSlice: 24^4 lattice, 4 dirs, 3x3 complex links (separate re/im fp32).
// MU=0, update EVEN parity sites of dir 0; everything else is a copy.
//
// Round 4: attack L1 wavefronts.
//  - matrix loads via 8B-aligned float2 windows (10 LDG.64 vs 18 LDG.32) + FSEL
//  - odd-site dir-0 copy moved to its own coalesced role
//  - complex math stays packed in fma.rn.f32x2

#define IDX9(d,t,z,y,x) ((((((d)*24+(t))*24+(z))*24+(y))*24+(x))*9)

static const int NSITE  = 24 * 24 * 24 * 12;          // even sites = 165888
static const int NCB    = NSITE / 128;                // 1296 compute blocks
static const int DIR_F  = 24 * 24 * 24 * 24 * 9;      // floats per direction
static const int COPY4  = 3 * DIR_F / 4;              // float4s in dirs 1..3
static const int PER_B  = 128 * 4;                    // float4s per copy block
static const int NCPB   = COPY4 / PER_B;              // 4374 copy blocks
static const int NODD_E = NSITE * 9;                  // odd complex elements
static const int NODDB  = NODD_E / (128 * 4);         // 2916 odd-copy blocks

typedef unsigned long long c64;   // packed {lo=re, hi=im} fp32 pair

__device__ __forceinline__ c64 pk(float lo, float hi) {
    c64 r; asm("mov.b64 %0,{%1,%2};" : "=l"(r) : "f"(lo), "f"(hi)); return r;
}
__device__ __forceinline__ void upk(c64 v, float &lo, float &hi) {
    asm("mov.b64 {%0,%1},%2;" : "=f"(lo), "=f"(hi) : "l"(v));
}
__device__ __forceinline__ c64 fma2(c64 a, c64 b, c64 c) {
    c64 d; asm("fma.rn.f32x2 %0,%1,%2,%3;" : "=l"(d) : "l"(a), "l"(b), "l"(c));
    return d;
}
__device__ __forceinline__ c64 mul2(c64 a, c64 b) {
    c64 d; asm("mul.rn.f32x2 %0,%1,%2;" : "=l"(d) : "l"(a), "l"(b)); return d;
}

struct C3 { c64 m[9]; };

// Windowed load: base b is 4B-aligned; a = b&~1 is 8B-aligned and [a, a+10)
// covers elements [b, b+9). 5 LDG.64 per array + FSEL select.
__device__ __forceinline__ void mload(C3 &A, const float* __restrict__ re,
                                      const float* __restrict__ im, int b) {
    int a = b & ~1;
    bool p = (b & 1) != 0;
    const float2* r2 = (const float2*)(re + a);
    const float2* i2 = (const float2*)(im + a);
    float fr[10], fi[10];
#pragma unroll
    for (int j = 0; j < 5; j++) {
        float2 vr = r2[j], vi = i2[j];
        fr[2*j] = vr.x; fr[2*j+1] = vr.y;
        fi[2*j] = vi.x; fi[2*j+1] = vi.y;
    }
#pragma unroll
    for (int i = 0; i < 9; i++)
        A.m[i] = pk(p ? fr[i+1] : fr[i], p ? fi[i+1] : fi[i]);
}

// MODE: 0 = A@B, 1 = A@B^dag, 2 = A^dag@B
template <int MODE>
__device__ __forceinline__ void cmul(C3 &C, const C3 &A, const C3 &B) {
#pragma unroll
    for (int r = 0; r < 3; r++) {
        float ar[3], ai[3];
#pragma unroll
        for (int k = 0; k < 3; k++)
            upk(A.m[MODE == 2 ? k * 3 + r : r * 3 + k], ar[k], ai[k]);
        c64 arr[3], aii[3];
#pragma unroll
        for (int k = 0; k < 3; k++) { arr[k] = pk(ar[k], ar[k]); aii[k] = pk(ai[k], ai[k]); }
#pragma unroll
        for (int c = 0; c < 3; c++) {
            c64 b0 = B.m[MODE == 1 ? c * 3 + 0 : 0 * 3 + c];
            c64 acc1 = mul2(arr[0], b0);
            c64 acc2 = mul2(aii[0], b0);
#pragma unroll
            for (int k = 1; k < 3; k++) {
                c64 b = B.m[MODE == 1 ? c * 3 + k : k * 3 + c];
                acc1 = fma2(arr[k], b, acc1);
                acc2 = fma2(aii[k], b, acc2);
            }
            float x1, y1, x2, y2;
            upk(acc1, x1, y1); upk(acc2, x2, y2);
            float cr, ci;
            if (MODE == 0)      { cr = x1 - y2; ci = y1 + x2; }
            else if (MODE == 1) { cr = x1 + y2; ci = x2 - y1; }
            else                { cr = x1 + y2; ci = y1 - x2; }
            C.m[r * 3 + c] = pk(cr, ci);
        }
    }
}

__device__ __forceinline__ void macc(C3 &F, const C3 &T, c64 cc) {
#pragma unroll
    for (int i = 0; i < 9; i++) F.m[i] = fma2(cc, T.m[i], F.m[i]);
}

// Forward staple (cf) + backward staple (cb) for one nu direction.
__device__ __forceinline__ void staple_pair(C3 &f,
        const float* __restrict__ xre, const float* __restrict__ xim,
        int b0p, int b0m, int bns, int bnsmu, int bnm, int bnmmu,
        c64 cf, c64 cb) {
    C3 A, B, C, T1, T2;
    mload(A, xre, xim, b0p);        // U0(s+nu)
    mload(B, xre, xim, bnsmu);      // Unu(s+mu)
    cmul<1>(T1, A, B);              // U0(s+nu) @ Unu(s+mu)^dag
    mload(C, xre, xim, bns);        // Unu(s)
    cmul<0>(T2, C, T1);
    macc(f, T2, cf);

    mload(A, xre, xim, bnm);        // Unu(s-nu)
    mload(B, xre, xim, b0m);        // U0(s-nu)
    cmul<2>(T1, A, B);              // Unu(s-nu)^dag @ U0(s-nu)
    mload(C, xre, xim, bnmmu);      // Unu(s-nu+mu)
    cmul<0>(T2, T1, C);
    macc(f, T2, cb);
}

__global__ __launch_bounds__(128, 6) void stout_fused(
        const float* __restrict__ xre,
        const float* __restrict__ xim,
        const float* __restrict__ coeff,
        float2* __restrict__ out) {
    if (blockIdx.x >= NCB) {
        int rb = blockIdx.x - NCB;
        if (rb < NCPB) {
            // ---- copy role: dirs 1..3, float4 interleave ----
            const float4* re4 = (const float4*)(xre + DIR_F);
            const float4* im4 = (const float4*)(xim + DIR_F);
            float4* o4 = (float4*)(out + DIR_F);
            int base = rb * PER_B + threadIdx.x;
#pragma unroll
            for (int k = 0; k < 4; k++) {
                int i = base + k * 128;
                float4 r = re4[i], m = im4[i];
                o4[2*i]     = make_float4(r.x, m.x, r.y, m.y);
                o4[2*i + 1] = make_float4(r.z, m.z, r.w, m.w);
            }
        } else {
            // ---- odd-site dir-0 copy role (coalesced-ish, ~50% density) ----
            int base = (rb - NCPB) * (128 * 4) + threadIdx.x;
#pragma unroll
            for (int k = 0; k < 4; k++) {
                int w = base + k * 128;          // odd-element linear index
                int s = w / 9, i = w - 9 * s;    // odd-site index, element
                int xi = s % 12; int r = s / 12;
                int y = r % 24; r /= 24;
                int z = r % 24; r /= 24;
                int t = r;
                int x = 2 * xi + (((t + z + y) & 1) ^ 1);   // odd parity
                int addr = IDX9(0, t, z, y, x) + i;
                out[addr] = make_float2(xre[addr], xim[addr]);
            }
        }
        return;
    }

    // ---- compute role: one even site ----
    int tid = blockIdx.x * 128 + threadIdx.x;
    int xi = tid % 12; int r = tid / 12;
    int y = r % 24; r /= 24;
    int z = r % 24; r /= 24;
    int t = r;
    int x = 2 * xi + ((t + z + y) & 1);      // (t+z+y+x) even

    c64* out64 = (c64*)out;

    int tp = (t + 1) % 24;
    int zp = (z + 1) % 24, zm = (z + 23) % 24;
    int yp = (y + 1) % 24, ym = (y + 23) % 24;
    int xp = (x + 1) % 24, xm = (x + 23) % 24;

    // scale_coeff(coeff,0.75) with the /6 staple average folded in
    c64 c[6];
#pragma unroll
    for (int i = 0; i < 6; i++) {
        float v = (0.47746482927568606f / 6.0f) * atanf(coeff[i]);
        c[i] = pk(v, v);
    }

    C3 f;
#pragma unroll
    for (int i = 0; i < 9; i++) f.m[i] = 0ull;

    staple_pair(f, xre, xim,                     // nu = 1 (Z)
                IDX9(0,t,zp,y,x), IDX9(0,t,zm,y,x),
                IDX9(1,t,z,y,x),  IDX9(1,tp,z,y,x),
                IDX9(1,t,zm,y,x), IDX9(1,tp,zm,y,x),
                c[0], c[1]);
    staple_pair(f, xre, xim,                     // nu = 2 (Y)
                IDX9(0,t,z,yp,x), IDX9(0,t,z,ym,x),
                IDX9(2,t,z,y,x),  IDX9(2,tp,z,y,x),
                IDX9(2,t,z,ym,x), IDX9(2,tp,z,ym,x),
                c[2], c[3]);
    staple_pair(f, xre, xim,                     // nu = 3 (X)
                IDX9(0,t,z,y,xp), IDX9(0,t,z,y,xm),
                IDX9(3,t,z,y,x),  IDX9(3,tp,z,y,x),
                IDX9(3,t,z,y,xm), IDX9(3,tp,z,y,xm),
                c[4], c[5]);

    int b0 = IDX9(0, t, z, y, x);
    C3 U0; mload(U0, xre, xim, b0);

    // Z = projectTangent(f @ U0^dag) scaled by 2^-4
    C3 Mm; cmul<1>(Mm, f, U0);
    float mr[9], mi[9];
#pragma unroll
    for (int i = 0; i < 9; i++) upk(Mm.m[i], mr[i], mi[i]);
    const float s = 0.03125f;   // 0.5 * 2^-4
    float zre[9], zim[9];
#pragma unroll
    for (int rr = 0; rr < 3; rr++)
#pragma unroll
        for (int cc = 0; cc < 3; cc++) {
            zre[rr*3+cc] = s * (mr[rr*3+cc] - mr[cc*3+rr]);
            zim[rr*3+cc] = s * (mi[rr*3+cc] + mi[cc*3+rr]);
        }
    float tri = (zim[0] + zim[4] + zim[8]) * (1.0f / 3.0f);
    zim[0] -= tri; zim[4] -= tri; zim[8] -= tri;
    C3 Z;
#pragma unroll
    for (int i = 0; i < 9; i++) Z.m[i] = pk(zre[i], zim[i]);

    // Horner Taylor, 12 terms: E = I + (Z@E)/k
    const c64 one = pk(1.0f, 0.0f);
    C3 E, T1;
#pragma unroll
    for (int i = 0; i < 9; i++) E.m[i] = (i % 4 == 0) ? one : 0ull;
#pragma unroll
    for (int k = 12; k >= 1; k--) {
        cmul<0>(T1, Z, E);
        float inv = 1.0f / (float)k;
        c64 inv2 = pk(inv, inv);
#pragma unroll
        for (int i = 0; i < 9; i++)
            E.m[i] = fma2(T1.m[i], inv2, (i % 4 == 0) ? one : 0ull);
    }
    // 4 squarings
#pragma unroll
    for (int sq = 0; sq < 4; sq++) { cmul<0>(T1, E, E); E = T1; }

    // y_mu = E @ U0 (even sites: xmu_fix = 0)
    C3 Y; cmul<0>(Y, E, U0);
#pragma unroll
    for (int i = 0; i < 9; i++) out64[b0 + i] = Y.m[i];
}

extern "C" void kernel_launch(void* const* d_in, const int* in_sizes, int n_in,
                              void* d_out, int out_size) {
    const float* xre   = (const float*)d_in[0];
    const float* xim   = (const float*)d_in[1];
    const float* coeff = (const float*)d_in[2];

    stout_fused<<<NCB + NCPB + NODDB, 128>>>(xre, xim, coeff, (float2*)d_out);
}